// round 1
// baseline (speedup 1.0000x reference)
#include <cuda_runtime.h>
#include <cstdint>
#include <math.h>

#define BATCH 8192
#define IN_F  1024
#define OUT_F 1024
#define NB    8                 // spline basis count (GRID_SIZE + SPLINE_ORDER)
#define KDIM  (IN_F * 9)        // 9216 augmented-K
#define NKNOTS 12

// Scratch (sanctioned: __device__ global arrays, no runtime allocation)
__device__ float g_A[(size_t)BATCH * KDIM];   // ~302 MB augmented activations (tf32-rounded)
__device__ float g_W[(size_t)KDIM * OUT_F];   // ~38 MB augmented weights (tf32-rounded)

__device__ __forceinline__ float tf32r(float x) {
    float r;
    asm("cvt.rna.tf32.f32 %0, %1;" : "=f"(r) : "f"(x));
    return r;
}

// ---------------------------------------------------------------------------
// Prep 1: augmented weights. Wg[(c*IN_F + i)*OUT_F + o]
//   c = 0      -> base_weight[o, i]
//   c = 1 + k  -> spline_weight[i, k, o] * spline_scaler[i, o]
// ---------------------------------------------------------------------------
__global__ void prep_w(const float* __restrict__ bw,
                       const float* __restrict__ sw,
                       const float* __restrict__ sc) {
    int idx = blockIdx.x * blockDim.x + threadIdx.x;   // exactly IN_F*OUT_F threads
    int i = idx / OUT_F;
    int o = idx - i * OUT_F;
    g_W[(size_t)i * OUT_F + o] = tf32r(bw[(size_t)o * IN_F + i]);
    float scale = sc[(size_t)i * OUT_F + o];
#pragma unroll
    for (int k = 0; k < NB; ++k) {
        g_W[((size_t)(1 + k) * IN_F + i) * OUT_F + o] =
            tf32r(sw[((size_t)i * NB + k) * OUT_F + o] * scale);
    }
}

// ---------------------------------------------------------------------------
// Prep 2: augmented activations. A[b, c*IN_F + i]:
//   c = 0     -> silu(x[b,i])
//   c = 1 + k -> Cox-de Boor cubic basis value k (8 values)
// Column layout c-major so the 9 writes per thread are each fully coalesced.
// ---------------------------------------------------------------------------
__global__ void prep_act(const float* __restrict__ x,
                         const float* __restrict__ grid) {
    __shared__ float t[NKNOTS];
    if (threadIdx.x < NKNOTS) t[threadIdx.x] = grid[threadIdx.x];  // all rows identical (jnp.tile)
    __syncthreads();

    int idx = blockIdx.x * blockDim.x + threadIdx.x;   // exactly BATCH*IN_F threads
    int b = idx / IN_F;
    int i = idx - b * IN_F;

    float xv = x[idx];
    float s = xv / (1.0f + expf(-xv));                 // silu

    float bas[11];
#pragma unroll
    for (int j = 0; j < 11; ++j)
        bas[j] = (xv >= t[j] && xv < t[j + 1]) ? 1.0f : 0.0f;
#pragma unroll
    for (int k = 1; k <= 3; ++k) {
#pragma unroll
        for (int j = 0; j < 11 - 3; ++j) {             // only first 11-k matter; extra iters harmless? no:
            // guard properly below
        }
    }
    // (explicit recursion, exact bounds)
#pragma unroll
    for (int j = 0; j < 10; ++j) {                     // k = 1
        float l = (xv - t[j]) / (t[j + 1] - t[j]);
        float r = (t[j + 2] - xv) / (t[j + 2] - t[j + 1]);
        bas[j] = l * bas[j] + r * bas[j + 1];
    }
#pragma unroll
    for (int j = 0; j < 9; ++j) {                      // k = 2
        float l = (xv - t[j]) / (t[j + 2] - t[j]);
        float r = (t[j + 3] - xv) / (t[j + 3] - t[j + 1]);
        bas[j] = l * bas[j] + r * bas[j + 1];
    }
#pragma unroll
    for (int j = 0; j < 8; ++j) {                      // k = 3
        float l = (xv - t[j]) / (t[j + 3] - t[j]);
        float r = (t[j + 4] - xv) / (t[j + 4] - t[j + 1]);
        bas[j] = l * bas[j] + r * bas[j + 1];
    }

    float* arow = g_A + (size_t)b * KDIM;
    arow[i] = tf32r(s);
#pragma unroll
    for (int k = 0; k < NB; ++k)
        arow[(size_t)(1 + k) * IN_F + i] = tf32r(bas[k]);
}

// ---------------------------------------------------------------------------
// GEMM: C[8192,1024] = A[8192,9216] @ W[9216,1024], tf32 mma.sync, fp32 accum
// CTA tile 128x128x32, 8 warps (2m x 4n), warp tile 64x32, double-buffer cp.async
// ---------------------------------------------------------------------------
#define BM 128
#define BN 128
#define BK 32
#define KITERS (KDIM / BK)        // 288
#define SA_STRIDE 36              // 32 + 4 pad -> conflict-free A frag loads
#define SB_STRIDE 136             // 128 + 8 pad -> conflict-free B frag loads
#define SA_SIZE (BM * SA_STRIDE)  // 4608 floats
#define SB_SIZE (BK * SB_STRIDE)  // 4352 floats
#define SMEM_BYTES ((2 * SA_SIZE + 2 * SB_SIZE) * sizeof(float))  // 71680

__device__ __forceinline__ void cp16(float* dst, const float* src) {
    uint32_t d = (uint32_t)__cvta_generic_to_shared(dst);
    asm volatile("cp.async.cg.shared.global [%0], [%1], 16;\n" :: "r"(d), "l"(src));
}

__device__ __forceinline__ void mma_tf32(float* c, const uint32_t* a, const uint32_t* b) {
    asm volatile(
        "mma.sync.aligned.m16n8k8.row.col.f32.tf32.tf32.f32 "
        "{%0,%1,%2,%3}, {%4,%5,%6,%7}, {%8,%9}, {%0,%1,%2,%3};\n"
        : "+f"(c[0]), "+f"(c[1]), "+f"(c[2]), "+f"(c[3])
        : "r"(a[0]), "r"(a[1]), "r"(a[2]), "r"(a[3]), "r"(b[0]), "r"(b[1]));
}

__device__ __forceinline__ void load_stage(float* dA, float* dB,
                                           int m0, int n0, int k0, int tid) {
#pragma unroll
    for (int it = 0; it < 4; ++it) {
        int chunk = tid + it * 256;
        int row = chunk >> 3, c4 = chunk & 7;          // A: 128 rows x 8 float4
        cp16(dA + row * SA_STRIDE + c4 * 4,
             g_A + (size_t)(m0 + row) * KDIM + k0 + c4 * 4);
    }
#pragma unroll
    for (int it = 0; it < 4; ++it) {
        int chunk = tid + it * 256;
        int row = chunk >> 5, c4 = chunk & 31;         // B: 32 rows x 32 float4
        cp16(dB + row * SB_STRIDE + c4 * 4,
             g_W + (size_t)(k0 + row) * OUT_F + n0 + c4 * 4);
    }
    asm volatile("cp.async.commit_group;\n" ::);
}

__global__ void __launch_bounds__(256, 2)
kan_gemm(float* __restrict__ C) {
    extern __shared__ float smem[];
    float* sA = smem;                 // 2 * SA_SIZE
    float* sB = smem + 2 * SA_SIZE;   // 2 * SB_SIZE

    const int tid = threadIdx.x;
    const int m0 = blockIdx.y * BM;
    const int n0 = blockIdx.x * BN;

    const int warp = tid >> 5, lane = tid & 31;
    const int wm = warp & 1;          // 0..1 -> 64 rows each
    const int wn = warp >> 1;         // 0..3 -> 32 cols each
    const int g = lane >> 2, tg = lane & 3;

    float acc[4][4][4];
#pragma unroll
    for (int a = 0; a < 4; ++a)
#pragma unroll
        for (int b = 0; b < 4; ++b)
#pragma unroll
            for (int c = 0; c < 4; ++c) acc[a][b][c] = 0.0f;

    load_stage(sA, sB, m0, n0, 0, tid);
    asm volatile("cp.async.wait_group 0;\n" ::);
    __syncthreads();

    for (int kt = 0; kt < KITERS; ++kt) {
        int s = kt & 1;
        if (kt + 1 < KITERS)
            load_stage(sA + (s ^ 1) * SA_SIZE, sB + (s ^ 1) * SB_SIZE,
                       m0, n0, (kt + 1) * BK, tid);

        const float* a = sA + s * SA_SIZE;
        const float* bsh = sB + s * SB_SIZE;

#pragma unroll
        for (int kk = 0; kk < 4; ++kk) {
            uint32_t af[4][4];
#pragma unroll
            for (int mt = 0; mt < 4; ++mt) {
                const float* ap = a + (wm * 64 + mt * 16 + g) * SA_STRIDE + kk * 8 + tg;
                af[mt][0] = __float_as_uint(ap[0]);
                af[mt][1] = __float_as_uint(ap[8 * SA_STRIDE]);
                af[mt][2] = __float_as_uint(ap[4]);
                af[mt][3] = __float_as_uint(ap[8 * SA_STRIDE + 4]);
            }
            uint32_t bf[4][2];
#pragma unroll
            for (int nt = 0; nt < 4; ++nt) {
                const float* bp = bsh + (kk * 8 + tg) * SB_STRIDE + wn * 32 + nt * 8 + g;
                bf[nt][0] = __float_as_uint(bp[0]);
                bf[nt][1] = __float_as_uint(bp[4 * SB_STRIDE]);
            }
#pragma unroll
            for (int mt = 0; mt < 4; ++mt)
#pragma unroll
                for (int nt = 0; nt < 4; ++nt)
                    mma_tf32(acc[mt][nt], af[mt], bf[nt]);
        }
        asm volatile("cp.async.wait_group 0;\n" ::);
        __syncthreads();
    }

    // Epilogue: fp32 out, float2 stores (cols 2*tg, 2*tg+1 contiguous)
#pragma unroll
    for (int mt = 0; mt < 4; ++mt) {
        int r0 = m0 + wm * 64 + mt * 16 + g;
#pragma unroll
        for (int nt = 0; nt < 4; ++nt) {
            int col = n0 + wn * 32 + nt * 8 + 2 * tg;
            *(float2*)(C + (size_t)r0 * OUT_F + col) =
                make_float2(acc[mt][nt][0], acc[mt][nt][1]);
            *(float2*)(C + (size_t)(r0 + 8) * OUT_F + col) =
                make_float2(acc[mt][nt][2], acc[mt][nt][3]);
        }
    }
}

// ---------------------------------------------------------------------------
extern "C" void kernel_launch(void* const* d_in, const int* in_sizes, int n_in,
                              void* d_out, int out_size) {
    const float* x    = (const float*)d_in[0];
    const float* grid = (const float*)d_in[1];
    const float* bw   = (const float*)d_in[2];
    const float* sw   = (const float*)d_in[3];
    const float* sc   = (const float*)d_in[4];
    float* out = (float*)d_out;

    prep_w<<<(IN_F * OUT_F) / 256, 256>>>(bw, sw, sc);
    prep_act<<<(BATCH * IN_F) / 256, 256>>>(x, grid);

    cudaFuncSetAttribute(kan_gemm, cudaFuncAttributeMaxDynamicSharedMemorySize,
                         (int)SMEM_BYTES);
    dim3 grd(OUT_F / BN, BATCH / BM);   // 8 x 64
    kan_gemm<<<grd, 256, SMEM_BYTES>>>(out);
}

// round 3
// speedup vs baseline: 1.7627x; 1.7627x over previous
#include <cuda_runtime.h>
#include <cuda_fp16.h>
#include <cstdint>
#include <math.h>

#define BATCH 8192
#define IN_F  1024
#define OUT_F 1024
#define NB    8
#define KDIM  (IN_F * 9)          // 9216
#define NKNOTS 12

// Scratch (__device__ globals — sanctioned)
__device__ __half g_Ah[(size_t)BATCH * KDIM];   // [b][c*1024+i]
__device__ __half g_Wh[(size_t)OUT_F * KDIM];   // [o][c*1024+i]  (B as [N,K])

// ---------------------------------------------------------------------------
// prep_w: augmented weights, transposed to [OUT_F, KDIM], fp16.
// ---------------------------------------------------------------------------
__global__ void prep_w(const float* __restrict__ bw,
                       const float* __restrict__ sw,
                       const float* __restrict__ sc) {
    __shared__ float tile[9][32][33];
    const int i0 = (blockIdx.x & 31) * 32;
    const int o0 = (blockIdx.x >> 5) * 32;
    const int tid = threadIdx.x;                 // 256

    { // c = 0 : base_weight[o, i] — coalesced over i
        int ti = tid & 31, to = tid >> 5;
#pragma unroll
        for (int p = 0; p < 4; ++p) {
            int ol = to + p * 8;
            tile[0][ol][ti] = bw[(size_t)(o0 + ol) * IN_F + i0 + ti];
        }
    }
    { // splines — coalesced over o
        int to = tid & 31, ti = tid >> 5;
#pragma unroll
        for (int p = 0; p < 4; ++p) {
            int il = ti + p * 8;
            int i = i0 + il;
            float scale = sc[(size_t)i * OUT_F + o0 + to];
#pragma unroll
            for (int k = 0; k < NB; ++k)
                tile[1 + k][to][il] = sw[((size_t)i * NB + k) * OUT_F + o0 + to] * scale;
        }
    }
    __syncthreads();
    { // write g_Wh[o][c*1024+i] — coalesced over i
        int il = tid & 31, ol0 = tid >> 5;
#pragma unroll
        for (int p = 0; p < 4; ++p) {
            int ol = ol0 + p * 8;
            size_t orow = (size_t)(o0 + ol) * KDIM;
#pragma unroll
            for (int c = 0; c < 9; ++c)
                g_Wh[orow + (size_t)c * IN_F + i0 + il] =
                    __float2half_rn(tile[c][ol][il]);
        }
    }
}

// ---------------------------------------------------------------------------
// prep_act: silu + 8 cubic B-spline bases, fp16
// ---------------------------------------------------------------------------
__global__ void prep_act(const float* __restrict__ x,
                         const float* __restrict__ grid) {
    __shared__ float t[NKNOTS];
    if (threadIdx.x < NKNOTS) t[threadIdx.x] = grid[threadIdx.x];
    __syncthreads();

    int idx = blockIdx.x * blockDim.x + threadIdx.x;
    int b = idx / IN_F;
    int i = idx - b * IN_F;

    float xv = x[idx];
    float s = xv / (1.0f + __expf(-xv));

    float bas[11];
#pragma unroll
    for (int j = 0; j < 11; ++j)
        bas[j] = (xv >= t[j] && xv < t[j + 1]) ? 1.0f : 0.0f;
#pragma unroll
    for (int j = 0; j < 10; ++j) {
        float l = (xv - t[j]) / (t[j + 1] - t[j]);
        float r = (t[j + 2] - xv) / (t[j + 2] - t[j + 1]);
        bas[j] = l * bas[j] + r * bas[j + 1];
    }
#pragma unroll
    for (int j = 0; j < 9; ++j) {
        float l = (xv - t[j]) / (t[j + 2] - t[j]);
        float r = (t[j + 3] - xv) / (t[j + 3] - t[j + 1]);
        bas[j] = l * bas[j] + r * bas[j + 1];
    }
#pragma unroll
    for (int j = 0; j < 8; ++j) {
        float l = (xv - t[j]) / (t[j + 3] - t[j]);
        float r = (t[j + 4] - xv) / (t[j + 4] - t[j + 1]);
        bas[j] = l * bas[j] + r * bas[j + 1];
    }

    __half* arow = g_Ah + (size_t)b * KDIM;
    arow[i] = __float2half_rn(s);
#pragma unroll
    for (int k = 0; k < NB; ++k)
        arow[(size_t)(1 + k) * IN_F + i] = __float2half_rn(bas[k]);
}

// ---------------------------------------------------------------------------
// fp16 GEMM: C[8192,1024] = A[8192,9216] @ W^T   (W stored [N,K])
// CTA 128x256xBK64, 512 thr (16 warps, warp tile 64x32), 3-stage cp.async,
// SW128-swizzled smem + ldmatrix fragments, mma.m16n8k16 f32 accum.
// ---------------------------------------------------------------------------
#define BM 128
#define BN 256
#define BK 64
#define KITERS (KDIM / BK)        // 144
#define STAGES 3
#define A_BYTES (BM * BK * 2)     // 16384
#define B_BYTES (BN * BK * 2)     // 32768
#define STG_BYTES (A_BYTES + B_BYTES)          // 49152
#define GEMM_SMEM (STAGES * STG_BYTES)         // 147456

__device__ __forceinline__ uint32_t smem_u32(const void* p) {
    uint32_t a;
    asm("{ .reg .u64 t; cvta.to.shared.u64 t, %1; cvt.u32.u64 %0, t; }" : "=r"(a) : "l"(p));
    return a;
}
__device__ __forceinline__ void cp16(uint32_t dst, const void* src) {
    asm volatile("cp.async.cg.shared.global [%0], [%1], 16;\n" :: "r"(dst), "l"(src));
}
__device__ __forceinline__ void ldsm_x4(uint32_t* r, uint32_t addr) {
    asm volatile("ldmatrix.sync.aligned.m8n8.x4.shared.b16 {%0,%1,%2,%3}, [%4];"
                 : "=r"(r[0]), "=r"(r[1]), "=r"(r[2]), "=r"(r[3]) : "r"(addr));
}
__device__ __forceinline__ void ldsm_x2(uint32_t* r, uint32_t addr) {
    asm volatile("ldmatrix.sync.aligned.m8n8.x2.shared.b16 {%0,%1}, [%2];"
                 : "=r"(r[0]), "=r"(r[1]) : "r"(addr));
}
__device__ __forceinline__ void mma_f16(float* c, const uint32_t* a, const uint32_t* b) {
    asm volatile(
        "mma.sync.aligned.m16n8k16.row.col.f32.f16.f16.f32 "
        "{%0,%1,%2,%3}, {%4,%5,%6,%7}, {%8,%9}, {%0,%1,%2,%3};\n"
        : "+f"(c[0]), "+f"(c[1]), "+f"(c[2]), "+f"(c[3])
        : "r"(a[0]), "r"(a[1]), "r"(a[2]), "r"(a[3]), "r"(b[0]), "r"(b[1]));
}

__device__ __forceinline__ void load_stage(uint32_t sbase, int slot,
                                           int m0, int n0, int k0, int tid) {
    uint32_t sd = sbase + slot * STG_BYTES;
#pragma unroll
    for (int t = 0; t < 2; ++t) {              // A: 1024 chunks of 16B
        int idx = tid + t * 512;
        int row = idx >> 3, c = idx & 7;
        cp16(sd + row * 128 + ((c ^ (row & 7)) << 4),
             g_Ah + (size_t)(m0 + row) * KDIM + k0 + c * 8);
    }
    uint32_t sdb = sd + A_BYTES;
#pragma unroll
    for (int t = 0; t < 4; ++t) {              // B: 2048 chunks of 16B
        int idx = tid + t * 512;
        int row = idx >> 3, c = idx & 7;
        cp16(sdb + row * 128 + ((c ^ (row & 7)) << 4),
             g_Wh + (size_t)(n0 + row) * KDIM + k0 + c * 8);
    }
}

__global__ void __launch_bounds__(512, 1)
kan_gemm(float* __restrict__ C) {
    extern __shared__ char smem[];
    const uint32_t sbase = smem_u32(smem);

    const int tid = threadIdx.x;
    const int warp = tid >> 5, lane = tid & 31;
    const int wm = warp & 1;          // 2 m-warps   -> 64 rows each
    const int wn = warp >> 1;         // 8 n-warps   -> 32 cols each
    const int g = lane >> 2, tg = lane & 3;
    const int m0 = blockIdx.y * BM;
    const int n0 = blockIdx.x * BN;

    // Per-lane ldmatrix address components (row fixed per mt/nt; chunk varies by kk)
    int a_row[4], b_row[4];
    const int a_kt = lane >> 4;               // A: ktile select (x4 layout)
    const int b_kt = (lane >> 3) & 1;         // B: ktile select (x2 layout)
#pragma unroll
    for (int mt = 0; mt < 4; ++mt) a_row[mt] = wm * 64 + mt * 16 + (lane & 15);
#pragma unroll
    for (int nt = 0; nt < 4; ++nt) b_row[nt] = wn * 32 + nt * 8 + (lane & 7);

    float acc[4][4][4];
#pragma unroll
    for (int a = 0; a < 4; ++a)
#pragma unroll
        for (int b = 0; b < 4; ++b)
#pragma unroll
            for (int c = 0; c < 4; ++c) acc[a][b][c] = 0.0f;

    // Prologue: stages 0,1
#pragma unroll
    for (int s = 0; s < STAGES - 1; ++s) {
        load_stage(sbase, s, m0, n0, s * BK, tid);
        asm volatile("cp.async.commit_group;\n" ::);
    }

    for (int it = 0; it < KITERS; ++it) {
        asm volatile("cp.async.wait_group %0;\n" :: "n"(STAGES - 2));
        __syncthreads();

        int ls = it + STAGES - 1;
        if (ls < KITERS)
            load_stage(sbase, ls % STAGES, m0, n0, ls * BK, tid);
        asm volatile("cp.async.commit_group;\n" ::);

        const uint32_t sa = sbase + (it % STAGES) * STG_BYTES;
        const uint32_t sb = sa + A_BYTES;

#pragma unroll
        for (int kk = 0; kk < BK / 16; ++kk) {
            uint32_t af[4][4], bf[4][2];
#pragma unroll
            for (int mt = 0; mt < 4; ++mt) {
                int r = a_row[mt];
                ldsm_x4(af[mt], sa + r * 128 + (((kk * 2 + a_kt) ^ (r & 7)) << 4));
            }
#pragma unroll
            for (int nt = 0; nt < 4; ++nt) {
                int r = b_row[nt];
                ldsm_x2(bf[nt], sb + r * 128 + (((kk * 2 + b_kt) ^ (r & 7)) << 4));
            }
#pragma unroll
            for (int mt = 0; mt < 4; ++mt)
#pragma unroll
                for (int nt = 0; nt < 4; ++nt)
                    mma_f16(acc[mt][nt], af[mt], bf[nt]);
        }
    }

    // Epilogue
#pragma unroll
    for (int mt = 0; mt < 4; ++mt) {
        int r0 = m0 + wm * 64 + mt * 16 + g;
#pragma unroll
        for (int nt = 0; nt < 4; ++nt) {
            int col = n0 + wn * 32 + nt * 8 + 2 * tg;
            *(float2*)(C + (size_t)r0 * OUT_F + col) =
                make_float2(acc[mt][nt][0], acc[mt][nt][1]);
            *(float2*)(C + (size_t)(r0 + 8) * OUT_F + col) =
                make_float2(acc[mt][nt][2], acc[mt][nt][3]);
        }
    }
}

// ---------------------------------------------------------------------------
extern "C" void kernel_launch(void* const* d_in, const int* in_sizes, int n_in,
                              void* d_out, int out_size) {
    const float* x    = (const float*)d_in[0];
    const float* grid = (const float*)d_in[1];
    const float* bw   = (const float*)d_in[2];
    const float* sw   = (const float*)d_in[3];
    const float* sc   = (const float*)d_in[4];
    float* out = (float*)d_out;

    prep_w<<<1024, 256>>>(bw, sw, sc);
    prep_act<<<(BATCH * IN_F) / 256, 256>>>(x, grid);

    cudaFuncSetAttribute(kan_gemm, cudaFuncAttributeMaxDynamicSharedMemorySize, GEMM_SMEM);
    dim3 grd(OUT_F / BN, BATCH / BM);   // 4 x 64 = 256 CTAs
    kan_gemm<<<grd, 512, GEMM_SMEM>>>(out);
}